// round 6
// baseline (speedup 1.0000x reference)
#include <cuda_runtime.h>
#include <cstdint>
#include <cstddef>

#define BATCH 256
#define SEQ   512
#define INDIM 32
#define H0 64
#define H1 128
#define H2 256

typedef unsigned long long ull;

__device__ float g_pre [(size_t)BATCH * SEQ * 4 * H2];
__device__ float g_x1  [(size_t)BATCH * SEQ * H0];
__device__ float g_x2  [(size_t)BATCH * SEQ * H1];
__device__ float g_x3  [(size_t)BATCH * SEQ * H2];

__device__ __forceinline__ float sigf(float x)  { return 1.f / (1.f + __expf(-x)); }
__device__ __forceinline__ float tanhfast(float x) { return 2.f / (1.f + __expf(-2.f * x)) - 1.f; }

__device__ __forceinline__ void ffma2(ull& d, ull a, ull b) {
    asm("fma.rn.f32x2 %0, %1, %2, %3;" : "=l"(d) : "l"(a), "l"(b), "l"(d));
}
__device__ __forceinline__ ull dup2(float w) {
    ull r; asm("mov.b64 %0, {%1, %1};" : "=l"(r) : "f"(w)); return r;
}
__device__ __forceinline__ ull pack2(float x, float y) {
    ull r; asm("mov.b64 %0, {%1, %2};" : "=l"(r) : "f"(x), "f"(y)); return r;
}
__device__ __forceinline__ void unpk(ull v, float& lo, float& hi) {
    asm("mov.b64 {%0, %1}, %2;" : "=f"(lo), "=f"(hi) : "l"(v));
}
__device__ __forceinline__ uint32_t cvta_s(const void* p) {
    return (uint32_t)__cvta_generic_to_shared(p);
}
__device__ __forceinline__ float lds32(uint32_t a) {
    float v; asm volatile("ld.shared.f32 %0, [%1];" : "=f"(v) : "r"(a)); return v;
}
__device__ __forceinline__ void lds2x64(uint32_t a, ull& x, ull& y) {
    asm volatile("ld.shared.v2.u64 {%0, %1}, [%2];" : "=l"(x), "=l"(y) : "r"(a));
}
__device__ __forceinline__ void sts32(uint32_t a, float v) {
    asm volatile("st.shared.f32 [%0], %1;" :: "r"(a), "f"(v));
}
__device__ __forceinline__ void stc32(uint32_t la, unsigned rank, float v) {
    uint32_t ra;
    asm("mapa.shared::cluster.u32 %0, %1, %2;" : "=r"(ra) : "r"(la), "r"(rank));
    asm volatile("st.shared::cluster.f32 [%0], %1;" :: "r"(ra), "f"(v) : "memory");
}
__device__ __forceinline__ void cluster_arrive_() {
    asm volatile("barrier.cluster.arrive.aligned;" ::: "memory");
}
__device__ __forceinline__ void cluster_wait_() {
    asm volatile("barrier.cluster.wait.aligned;" ::: "memory");
}
__device__ __forceinline__ void cluster_sync_() { cluster_arrive_(); cluster_wait_(); }

// ---------------- input GEMM: C = X @ W^T + bih + bhh (FFMA2 inner loop) --------
template <int K, int N>
__global__ void __launch_bounds__(256) gemm_pre_kernel(
    const float* __restrict__ X, const float* __restrict__ W,
    const float* __restrict__ bih, const float* __restrict__ bhh,
    float* __restrict__ C)
{
    constexpr int BM = 128, BN = 64, BK = 32;
    __shared__ float Xs[BK * BM];
    __shared__ float Wt[BK * BN];
    const int m0 = blockIdx.x * BM, n0 = blockIdx.y * BN, tid = threadIdx.x;

    ull acc2[4][4];   // [m-pair][n]
#pragma unroll
    for (int p = 0; p < 4; p++)
#pragma unroll
        for (int n = 0; n < 4; n++) acc2[p][n] = 0ull;

    const int tm = (tid >> 4) << 3;
    const int tn = (tid & 15) << 2;
    const uint32_t xsb = cvta_s(Xs);

    for (int k0 = 0; k0 < K; k0 += BK) {
#pragma unroll
        for (int i = 0; i < 4; i++) {
            int f4 = tid + i * 256, row = f4 >> 3, kk = (f4 & 7) << 2;
            float4 v = *reinterpret_cast<const float4*>(&X[(size_t)(m0 + row) * K + k0 + kk]);
            Xs[(kk + 0) * BM + row] = v.x; Xs[(kk + 1) * BM + row] = v.y;
            Xs[(kk + 2) * BM + row] = v.z; Xs[(kk + 3) * BM + row] = v.w;
        }
#pragma unroll
        for (int i = 0; i < 2; i++) {
            int f4 = tid + i * 256, row = f4 >> 3, kk = (f4 & 7) << 2;
            float4 v = *reinterpret_cast<const float4*>(&W[(size_t)(n0 + row) * K + k0 + kk]);
            Wt[(kk + 0) * BN + row] = v.x; Wt[(kk + 1) * BN + row] = v.y;
            Wt[(kk + 2) * BN + row] = v.z; Wt[(kk + 3) * BN + row] = v.w;
        }
        __syncthreads();
#pragma unroll
        for (int kk = 0; kk < BK; kk++) {
            ull a[4];
            lds2x64(xsb + (uint32_t)(kk * BM + tm) * 4u,     a[0], a[1]);
            lds2x64(xsb + (uint32_t)(kk * BM + tm + 4) * 4u, a[2], a[3]);
            float4 b = *reinterpret_cast<const float4*>(&Wt[kk * BN + tn]);
            ull bd[4] = {dup2(b.x), dup2(b.y), dup2(b.z), dup2(b.w)};
#pragma unroll
            for (int p = 0; p < 4; p++)
#pragma unroll
                for (int n = 0; n < 4; n++) ffma2(acc2[p][n], a[p], bd[n]);
        }
        __syncthreads();
    }

    float bb4[4];
#pragma unroll
    for (int n = 0; n < 4; n++) bb4[n] = bih[n0 + tn + n] + bhh[n0 + tn + n];
#pragma unroll
    for (int p = 0; p < 4; p++) {
        float e0[4], e1[4];
#pragma unroll
        for (int n = 0; n < 4; n++) unpk(acc2[p][n], e0[n], e1[n]);
        float4 o0 = {e0[0] + bb4[0], e0[1] + bb4[1], e0[2] + bb4[2], e0[3] + bb4[3]};
        float4 o1 = {e1[0] + bb4[0], e1[1] + bb4[1], e1[2] + bb4[2], e1[3] + bb4[3]};
        *reinterpret_cast<float4*>(&C[(size_t)(m0 + tm + 2 * p + 0) * N + n0 + tn]) = o0;
        *reinterpret_cast<float4*>(&C[(size_t)(m0 + tm + 2 * p + 1) * N + n0 + tn]) = o1;
    }
}

// ---------------- LSTM recurrence: batch-major warps, gate-pair f32x2 ----------
// Block 256 = JS hidden units x (NB/BB) batch-groups; thread = (j, bgrp) owns
// all 4 gates of unit j for BB batches; tid = bgrp + NBGp*j so a warp shares few
// j (weight broadcast) across many batches. Gates ride f32x2 lanes as (i,f),(g,o)
// loaded directly from smem (no dup); h is scalar in smem (padded NBP), dup'd by
// one MOV. pre(t) is folded into accumulator init (prefetched one step ahead).
// h exchanged via st.shared::cluster + split cluster barrier.
template <int H, int G, int NB, int BB>
__global__ void __launch_bounds__(256) lstm_recur_kernel(
    const float* __restrict__ pre, const float* __restrict__ Whh,
    float* __restrict__ xout)
{
    constexpr int JS   = H / G;
    constexpr int NBGp = NB / BB;
    constexpr int NBP  = NB + 1;          // odd pad: conflict-free h stores
    static_assert(JS * NBGp == 256, "map");

    extern __shared__ float sm[];
    float* Ws = sm;                        // [H][JS][4]
    float* hs = Ws + H * JS * 4;           // [2][H][NBP]

    const int tid   = threadIdx.x;
    const int bgrp  = tid % NBGp;
    const int j     = tid / NBGp;
    const int bbase = bgrp * BB;
    const int grp   = (G > 1) ? (blockIdx.x / G) : blockIdx.x;
    const int sl    = (G > 1) ? (blockIdx.x % G) : 0;
    const int b0    = grp * NB;
    const int j0    = sl * JS;

    // Whh slice -> Ws[k][jj][gate]
    for (int gj = 0; gj < 4 * JS; gj++) {
        const int g = gj / JS, jj = gj % JS;
        const float* src = Whh + (size_t)(g * H + j0 + jj) * H;
        for (int k = tid; k < H; k += 256)
            Ws[(k * JS + jj) * 4 + g] = src[k];
    }
    for (int i = tid; i < 2 * H * NBP; i += 256) hs[i] = 0.f;
    __syncthreads();
    if (G > 1) cluster_sync_();

    const uint32_t hsb = cvta_s(hs);
    const uint32_t wsb = cvta_s(Ws);

    const float* pp[BB];
    float* xo[BB];
    float pin[BB][4];
    float c[BB];
#pragma unroll
    for (int b = 0; b < BB; b++) {
        c[b] = 0.f;
        pp[b] = pre + (size_t)(b0 + bbase + b) * SEQ * (4 * H) + j0 + j;
        xo[b] = xout + (size_t)(b0 + bbase + b) * SEQ * H + j0 + j;
#pragma unroll
        for (int g = 0; g < 4; g++) pin[b][g] = __ldcs(pp[b] + g * H);
    }

    for (int t = 0; t < SEQ; t++) {
        const uint32_t hb = hsb + (uint32_t)((t & 1) * H * NBP) * 4u;

        // acc init = pre(t)  (gate pairs (i,f),(g,o))
        ull acc[BB][2];
#pragma unroll
        for (int b = 0; b < BB; b++) {
            acc[b][0] = pack2(pin[b][0], pin[b][1]);
            acc[b][1] = pack2(pin[b][2], pin[b][3]);
        }

        // dot over H
#pragma unroll 8
        for (int k = 0; k < H; k++) {
            ull wp0, wp1;
            lds2x64(wsb + (uint32_t)(k * JS + j) * 16u, wp0, wp1);
            const uint32_t ha = hb + (uint32_t)(k * NBP + bbase) * 4u;
#pragma unroll
            for (int b = 0; b < BB; b++) {
                const ull hd = dup2(lds32(ha + b * 4u));
                ffma2(acc[b][0], hd, wp0);
                ffma2(acc[b][1], hd, wp1);
            }
        }

        // activations + h store
        const uint32_t wb = hsb + (uint32_t)((((t + 1) & 1) * H + j0 + j) * NBP + bbase) * 4u;
#pragma unroll
        for (int b = 0; b < BB; b++) {
            float si, sf, sg, so;
            unpk(acc[b][0], si, sf);
            unpk(acc[b][1], sg, so);
            c[b] = sigf(sf) * c[b] + sigf(si) * tanhfast(sg);
            const float h = sigf(so) * tanhfast(c[b]);
            xo[b][(size_t)t * H] = h;
            if (G == 1) {
                sts32(wb + b * 4u, h);
            } else {
#pragma unroll
                for (unsigned dst = 0; dst < G; dst++) stc32(wb + b * 4u, dst, h);
            }
        }

        if (G > 1) cluster_arrive_();

        // prefetch pre(t+1) under the barrier
        const int tn = (t + 1 < SEQ) ? t + 1 : t;
#pragma unroll
        for (int b = 0; b < BB; b++)
#pragma unroll
            for (int g = 0; g < 4; g++)
                pin[b][g] = __ldcs(pp[b] + (size_t)tn * 4 * H + g * H);

        if (G > 1) cluster_wait_();
        else       __syncthreads();
    }
}

// ---------------- final linear (OUT_DIM=1) + tanh ----------------
__global__ void __launch_bounds__(256) final_kernel(
    const float* __restrict__ x3, const float* __restrict__ Wl,
    const float* __restrict__ bl, float* __restrict__ out)
{
    int warp = (blockIdx.x * 256 + threadIdx.x) >> 5;
    int lane = threadIdx.x & 31;
    const float* xr = x3 + (size_t)warp * H2;
    float acc = 0.f;
#pragma unroll
    for (int i = 0; i < 8; i++) acc += xr[i * 32 + lane] * __ldg(&Wl[i * 32 + lane]);
#pragma unroll
    for (int off = 16; off; off >>= 1) acc += __shfl_xor_sync(0xffffffffu, acc, off);
    if (lane == 0) out[warp] = tanhf(acc + bl[0]);
}

// ---------------- launch ----------------
template <typename KernT>
static void launch_cluster(KernT kern, int grid, int G, int smem,
                           const float* pre, const float* Whh, float* xout)
{
    cudaLaunchConfig_t cfg = {};
    cfg.gridDim = dim3(grid, 1, 1);
    cfg.blockDim = dim3(256, 1, 1);
    cfg.dynamicSmemBytes = smem;
    cfg.stream = 0;
    cudaLaunchAttribute attr[1];
    attr[0].id = cudaLaunchAttributeClusterDimension;
    attr[0].val.clusterDim.x = G;
    attr[0].val.clusterDim.y = 1;
    attr[0].val.clusterDim.z = 1;
    cfg.attrs = attr;
    cfg.numAttrs = 1;
    cudaLaunchKernelEx(&cfg, kern, pre, Whh, xout);
}

extern "C" void kernel_launch(void* const* d_in, const int* in_sizes, int n_in,
                              void* d_out, int out_size)
{
    const float* noise = (const float*)d_in[0];
    const float* Wih0 = (const float*)d_in[1];
    const float* Whh0 = (const float*)d_in[2];
    const float* bih0 = (const float*)d_in[3];
    const float* bhh0 = (const float*)d_in[4];
    const float* Wih1 = (const float*)d_in[5];
    const float* Whh1 = (const float*)d_in[6];
    const float* bih1 = (const float*)d_in[7];
    const float* bhh1 = (const float*)d_in[8];
    const float* Wih2 = (const float*)d_in[9];
    const float* Whh2 = (const float*)d_in[10];
    const float* bih2 = (const float*)d_in[11];
    const float* bhh2 = (const float*)d_in[12];
    const float* Wl   = (const float*)d_in[13];
    const float* bl   = (const float*)d_in[14];
    float* out = (float*)d_out;

    float *pre, *x1, *x2, *x3;
    cudaGetSymbolAddress((void**)&pre, g_pre);
    cudaGetSymbolAddress((void**)&x1,  g_x1);
    cudaGetSymbolAddress((void**)&x2,  g_x2);
    cudaGetSymbolAddress((void**)&x3,  g_x3);

    // smem = Ws[H][JS][4] + hs[2][H][NB+1] floats
    const int smem0 = (H0 * 64 * 4 + 2 * H0 * 5) * 4;    //  68,096
    const int smem1 = (H1 * 64 * 4 + 2 * H1 * 5) * 4;    // 136,192
    const int smem2 = (H2 * 32 * 4 + 2 * H2 * 17) * 4;   // 165,888

    cudaFuncSetAttribute(lstm_recur_kernel<H0, 1, 4, 1>,
                         cudaFuncAttributeMaxDynamicSharedMemorySize, smem0);
    cudaFuncSetAttribute(lstm_recur_kernel<H1, 2, 4, 1>,
                         cudaFuncAttributeMaxDynamicSharedMemorySize, smem1);
    cudaFuncSetAttribute(lstm_recur_kernel<H2, 8, 16, 2>,
                         cudaFuncAttributeMaxDynamicSharedMemorySize, smem2);

    const int MBLK = (BATCH * SEQ) / 128;

    gemm_pre_kernel<INDIM, 4 * H0><<<dim3(MBLK, (4 * H0) / 64), 256>>>(noise, Wih0, bih0, bhh0, pre);
    lstm_recur_kernel<H0, 1, 4, 1><<<64, 256, smem0>>>(pre, Whh0, x1);

    gemm_pre_kernel<H0, 4 * H1><<<dim3(MBLK, (4 * H1) / 64), 256>>>(x1, Wih1, bih1, bhh1, pre);
    launch_cluster(lstm_recur_kernel<H1, 2, 4, 1>, 128, 2, smem1, pre, Whh1, x2);

    gemm_pre_kernel<H1, 4 * H2><<<dim3(MBLK, (4 * H2) / 64), 256>>>(x2, Wih2, bih2, bhh2, pre);
    launch_cluster(lstm_recur_kernel<H2, 8, 16, 2>, 128, 8, smem2, pre, Whh2, x3);

    final_kernel<<<(BATCH * SEQ) / 8, 256>>>(x3, Wl, bl, out);
}